// round 2
// baseline (speedup 1.0000x reference)
#include <cuda_runtime.h>
#include <math.h>

#define N_TOK 65536
#define DIM   256
#define KEMB  1024
#define BM 128
#define BN 128
#define BK 16

// ---- scratch (no allocation allowed) ----
__device__ float g_enorm[KEMB];
__device__ int   g_idx[N_TOK];
__device__ float g_tokloss[N_TOK];
__device__ int   g_hist[KEMB];

// ---------------------------------------------------------------------------
// Kernel 1: ||e_k||^2 for all codewords; also zero the histogram.
// ---------------------------------------------------------------------------
__global__ void enorm_kernel(const float* __restrict__ E) {
    int warp = threadIdx.x >> 5;
    int lane = threadIdx.x & 31;
    int row  = blockIdx.x * 8 + warp;          // 128 blocks * 8 warps = 1024 rows

    const float* r = E + (size_t)row * DIM;
    float s = 0.f;
    #pragma unroll
    for (int i = 0; i < DIM / 32; i++) {
        float v = r[lane + i * 32];
        s = fmaf(v, v, s);
    }
    #pragma unroll
    for (int o = 16; o > 0; o >>= 1) s += __shfl_xor_sync(0xFFFFFFFFu, s, o);
    if (lane == 0) g_enorm[row] = s;

    int gid = blockIdx.x * blockDim.x + threadIdx.x;
    if (gid < KEMB) g_hist[gid] = 0;
}

// ---------------------------------------------------------------------------
// Kernel 2: fused distances + argmin (exact fp32; matches jnp argmin).
// ---------------------------------------------------------------------------
__global__ __launch_bounds__(256, 2)
void vq_argmin_kernel(const float* __restrict__ X, const float* __restrict__ E) {
    __shared__ float Xs[BK][BM + 4];
    __shared__ float Es[BK][BN + 4];
    __shared__ float s_enorm[KEMB];
    __shared__ float s_val[BM][16];
    __shared__ int   s_idx[BM][16];

    const int tid = threadIdx.x;
    const int tx  = tid & 15;
    const int ty  = tid >> 4;
    const int brow = blockIdx.x * BM;

    #pragma unroll
    for (int i = 0; i < KEMB / 256; i++) s_enorm[tid + i * 256] = g_enorm[tid + i * 256];

    float best[8];
    int   bidx[8];
    #pragma unroll
    for (int i = 0; i < 8; i++) { best[i] = 3.0e38f; bidx[i] = 0; }

    // tile-load slots: 512 float4 per 128x16 tile, 2 per thread
    const int s0 = tid;
    const int s1 = tid + 256;
    const int r0 = s0 >> 2, c0 = (s0 & 3) * 4;
    const int r1 = s1 >> 2, c1 = (s1 & 3) * 4;

    for (int cb = 0; cb < KEMB / BN; cb++) {
        const float* Eb = E + (size_t)cb * BN * DIM;

        float acc[8][8];
        #pragma unroll
        for (int i = 0; i < 8; i++)
            #pragma unroll
            for (int j = 0; j < 8; j++) acc[i][j] = 0.f;

        for (int dk = 0; dk < DIM; dk += BK) {
            float4 xa = *(const float4*)(X  + (size_t)(brow + r0) * DIM + dk + c0);
            float4 xb = *(const float4*)(X  + (size_t)(brow + r1) * DIM + dk + c1);
            float4 ea = *(const float4*)(Eb + (size_t)r0 * DIM + dk + c0);
            float4 eb = *(const float4*)(Eb + (size_t)r1 * DIM + dk + c1);

            __syncthreads();   // previous iteration's readers done
            Xs[c0 + 0][r0] = xa.x; Xs[c0 + 1][r0] = xa.y;
            Xs[c0 + 2][r0] = xa.z; Xs[c0 + 3][r0] = xa.w;
            Xs[c1 + 0][r1] = xb.x; Xs[c1 + 1][r1] = xb.y;
            Xs[c1 + 2][r1] = xb.z; Xs[c1 + 3][r1] = xb.w;
            Es[c0 + 0][r0] = ea.x; Es[c0 + 1][r0] = ea.y;
            Es[c0 + 2][r0] = ea.z; Es[c0 + 3][r0] = ea.w;
            Es[c1 + 0][r1] = eb.x; Es[c1 + 1][r1] = eb.y;
            Es[c1 + 2][r1] = eb.z; Es[c1 + 3][r1] = eb.w;
            __syncthreads();

            #pragma unroll
            for (int k = 0; k < BK; k++) {
                float xr[8], er[8];
                *(float4*)(xr)     = *(const float4*)&Xs[k][ty * 4];
                *(float4*)(xr + 4) = *(const float4*)&Xs[k][64 + ty * 4];
                *(float4*)(er)     = *(const float4*)&Es[k][tx * 4];
                *(float4*)(er + 4) = *(const float4*)&Es[k][64 + tx * 4];
                #pragma unroll
                for (int i = 0; i < 8; i++)
                    #pragma unroll
                    for (int j = 0; j < 8; j++)
                        acc[i][j] = fmaf(xr[i], er[j], acc[i][j]);
            }
        }

        // running-min epilogue (ascending cj within tile; tiles ascend -> the
        // strict < keeps the first minimum, matching jnp.argmin)
        #pragma unroll
        for (int j = 0; j < 8; j++) {
            int cj = cb * BN + ((j < 4) ? (tx * 4 + j) : (64 + tx * 4 + (j - 4)));
            float en = s_enorm[cj];
            #pragma unroll
            for (int i = 0; i < 8; i++) {
                float d = fmaf(-2.f, acc[i][j], en);
                if (d < best[i]) { best[i] = d; bidx[i] = cj; }
            }
        }
    }

    __syncthreads();
    #pragma unroll
    for (int i = 0; i < 8; i++) {
        int ri = (i < 4) ? (ty * 4 + i) : (64 + ty * 4 + (i - 4));
        s_val[ri][tx] = best[i];
        s_idx[ri][tx] = bidx[i];
    }
    __syncthreads();

    if (tid < BM) {
        float bv = s_val[tid][0];
        int   bi = s_idx[tid][0];
        #pragma unroll
        for (int t = 1; t < 16; t++) {
            float v  = s_val[tid][t];
            int   ix = s_idx[tid][t];
            if (v < bv || (v == bv && ix < bi)) { bv = v; bi = ix; }
        }
        g_idx[brow + tid] = bi;
    }
}

// ---------------------------------------------------------------------------
// Kernel 3: per-token epilogue.  One block (256 thr) per token.
// NOTE: out_enc is only 8-byte aligned (layout offset 2+N*D+N is even but not
// a multiple of 4 floats) -> use float2 stores, NOT float4.
// ---------------------------------------------------------------------------
__global__ __launch_bounds__(256)
void vq_epilogue_kernel(const float* __restrict__ X, const float* __restrict__ E,
                        float* __restrict__ out_q, float* __restrict__ out_idx,
                        float* __restrict__ out_enc) {
    const int t   = blockIdx.x;
    const int tid = threadIdx.x;
    const int idx = g_idx[t];

    if (tid == 0) {
        atomicAdd(&g_hist[idx], 1);
        out_idx[t] = (float)idx;
    }

    float q = E[(size_t)idx * DIM + tid];
    float x = X[(size_t)t   * DIM + tid];
    out_q[(size_t)t * DIM + tid] = q;

    // encodings row: 1024 floats, 4 per thread as two float2 stores (8B aligned)
    float2 v0 = make_float2(0.f, 0.f);
    float2 v1 = make_float2(0.f, 0.f);
    if ((idx >> 2) == tid) {
        int sub = idx & 3;
        if (sub == 0) v0.x = 1.f;
        else if (sub == 1) v0.y = 1.f;
        else if (sub == 2) v1.x = 1.f;
        else v1.y = 1.f;
    }
    float* erow = out_enc + (size_t)t * KEMB + tid * 4;
    *(float2*)(erow)     = v0;
    *(float2*)(erow + 2) = v1;

    // loss partial
    float d  = q - x;
    float sq = d * d;
    #pragma unroll
    for (int o = 16; o > 0; o >>= 1) sq += __shfl_xor_sync(0xFFFFFFFFu, sq, o);
    __shared__ float ws[8];
    if ((tid & 31) == 0) ws[tid >> 5] = sq;
    __syncthreads();
    if (tid == 0) {
        float s = 0.f;
        #pragma unroll
        for (int i = 0; i < 8; i++) s += ws[i];
        g_tokloss[t] = s;
    }
}

// ---------------------------------------------------------------------------
// Kernel 4: finalize loss + perplexity (deterministic double reductions).
// ---------------------------------------------------------------------------
__global__ __launch_bounds__(256)
void vq_finalize_kernel(float* __restrict__ out_loss, float* __restrict__ out_perp) {
    __shared__ double sm[256];
    const int tid = threadIdx.x;

    double s = 0.0;
    for (int i = tid; i < N_TOK; i += 256) s += (double)g_tokloss[i];
    sm[tid] = s;
    __syncthreads();
    for (int st = 128; st > 0; st >>= 1) {
        if (tid < st) sm[tid] += sm[tid + st];
        __syncthreads();
    }
    if (tid == 0)
        out_loss[0] = (float)(0.25 * sm[0] / ((double)N_TOK * (double)DIM));
    __syncthreads();

    double p = 0.0;
    for (int i = tid; i < KEMB; i += 256) {
        double pk = (double)g_hist[i] / (double)N_TOK;
        p += pk * log(pk + 1e-10);
    }
    sm[tid] = p;
    __syncthreads();
    for (int st = 128; st > 0; st >>= 1) {
        if (tid < st) sm[tid] += sm[tid + st];
        __syncthreads();
    }
    if (tid == 0)
        out_perp[0] = (float)exp(-sm[0]);
}

// ---------------------------------------------------------------------------
extern "C" void kernel_launch(void* const* d_in, const int* in_sizes, int n_in,
                              void* d_out, int out_size) {
    const float* X = (const float*)d_in[0];
    const float* E = (const float*)d_in[1];
    // defensive: pick by size if the order differs
    if (n_in >= 2 && in_sizes[0] == KEMB * DIM && in_sizes[1] == N_TOK * DIM) {
        const float* tmp = X; X = E; E = tmp;
    }

    float* out      = (float*)d_out;
    float* out_loss = out;                                   // 1
    float* out_q    = out + 1;                               // N*D
    float* out_idx  = out + 1 + (size_t)N_TOK * DIM;         // N
    float* out_perp = out_idx + N_TOK;                       // 1
    float* out_enc  = out_perp + 1;                          // N*K

    enorm_kernel      <<<128, 256>>>(E);
    vq_argmin_kernel  <<<N_TOK / BM, 256>>>(X, E);
    vq_epilogue_kernel<<<N_TOK, 256>>>(X, E, out_q, out_idx, out_enc);
    vq_finalize_kernel<<<1, 256>>>(out_loss, out_perp);
}

// round 6
// speedup vs baseline: 1.4589x; 1.4589x over previous
#include <cuda_runtime.h>
#include <cuda_bf16.h>
#include <math.h>
#include <stdint.h>

#define N_TOK 65536
#define DIM   256
#define KEMB  1024
#define MARGIN 0.6f

// ======================= helpers ===========================================
__device__ __forceinline__ uint32_t smem_to_u32(const void* p) {
    uint32_t a;
    asm("{ .reg .u64 t; cvta.to.shared.u64 t, %1; cvt.u32.u64 %0, t; }"
        : "=r"(a) : "l"(p));
    return a;
}
#define CP_ASYNC16(dst, src) \
    asm volatile("cp.async.cg.shared.global [%0], [%1], 16;" :: "r"(dst), "l"(src))
#define CP_COMMIT() asm volatile("cp.async.commit_group;" ::: "memory")
#define CP_WAIT(n)  asm volatile("cp.async.wait_group %0;" :: "n"(n) : "memory")

__device__ __forceinline__ void ldm_x4(uint32_t* r, uint32_t addr) {
    asm volatile("ldmatrix.sync.aligned.m8n8.x4.shared.b16 {%0,%1,%2,%3}, [%4];"
        : "=r"(r[0]), "=r"(r[1]), "=r"(r[2]), "=r"(r[3]) : "r"(addr));
}
__device__ __forceinline__ void mma_bf16(float* c, const uint32_t* a,
                                         uint32_t b0, uint32_t b1) {
    asm volatile(
        "mma.sync.aligned.m16n8k16.row.col.f32.bf16.bf16.f32 "
        "{%0,%1,%2,%3}, {%4,%5,%6,%7}, {%8,%9}, {%0,%1,%2,%3};"
        : "+f"(c[0]), "+f"(c[1]), "+f"(c[2]), "+f"(c[3])
        : "r"(a[0]), "r"(a[1]), "r"(a[2]), "r"(a[3]), "r"(b0), "r"(b1));
}

// ======================= device scratch ====================================
__device__ __align__(256) __nv_bfloat16 g_xhi[(size_t)N_TOK * DIM];
__device__ __align__(256) __nv_bfloat16 g_xlo[(size_t)N_TOK * DIM];
__device__ __align__(256) __nv_bfloat16 g_ehi[(size_t)KEMB * DIM];
__device__ float g_enorm[KEMB];
__device__ int   g_idx[N_TOK];
__device__ float g_tokloss[N_TOK];
__device__ int   g_hist[KEMB];
__device__ int   g_nrcnt;
__device__ int   g_rlist[N_TOK];

// ======================= kernel 0: X split-bf16 conversion =================
__global__ __launch_bounds__(256)
void convert_kernel(const float* __restrict__ X) {
    size_t i = (size_t)blockIdx.x * 256 + threadIdx.x;   // float4 index
    float4 v = ((const float4*)X)[i];
    union { __nv_bfloat16 h[4]; uint2 u; } hi, lo;
    hi.h[0] = __float2bfloat16(v.x); lo.h[0] = __float2bfloat16(v.x - __bfloat162float(hi.h[0]));
    hi.h[1] = __float2bfloat16(v.y); lo.h[1] = __float2bfloat16(v.y - __bfloat162float(hi.h[1]));
    hi.h[2] = __float2bfloat16(v.z); lo.h[2] = __float2bfloat16(v.z - __bfloat162float(hi.h[2]));
    hi.h[3] = __float2bfloat16(v.w); lo.h[3] = __float2bfloat16(v.w - __bfloat162float(hi.h[3]));
    ((uint2*)g_xhi)[i] = hi.u;
    ((uint2*)g_xlo)[i] = lo.u;
}

// ======================= kernel 1: ||e||^2 + E->bf16 + zeroing =============
__global__ __launch_bounds__(256)
void enorm_kernel(const float* __restrict__ E) {
    int warp = threadIdx.x >> 5;
    int lane = threadIdx.x & 31;
    int row  = blockIdx.x * 8 + warp;

    const float* r = E + (size_t)row * DIM;
    float s = 0.f;
    #pragma unroll
    for (int i = 0; i < DIM / 32; i++) {
        float v = r[lane + i * 32];
        g_ehi[(size_t)row * DIM + lane + i * 32] = __float2bfloat16(v);
        s = fmaf(v, v, s);
    }
    #pragma unroll
    for (int o = 16; o > 0; o >>= 1) s += __shfl_xor_sync(0xFFFFFFFFu, s, o);
    if (lane == 0) g_enorm[row] = s;

    int gid = blockIdx.x * blockDim.x + threadIdx.x;
    if (gid < KEMB) g_hist[gid] = 0;
    if (gid == 0)   g_nrcnt = 0;
}

// ======================= kernel 2: mma.sync distances + argmin =============
// 128 tokens / CTA.  A (xhi,xlo) resident in SMEM, padded stride 264 bf16.
// B (ehi) streamed: chunks of 128 codewords x 64 k, stride 88 bf16,
// double-buffered cp.async.  8 warps: wm=wid&3 (32 rows), wn=wid>>2 (64 cols).
#define A_STRIDE 264      // bf16, *2 = 528 B  (33*16: 16B aligned, bank-clean)
#define B_STRIDE 88       // bf16, *2 = 176 B  (11*16: 16B aligned, bank-clean)
#define A_SLAB   (128 * A_STRIDE * 2)       // 67584 B per (hi|lo) slab
#define B_CHUNK  (128 * B_STRIDE * 2)       // 22528 B per chunk
#define OFF_EN   0
#define OFF_A    4096
#define OFF_B    (OFF_A + 2 * A_SLAB)       // 139264
#define GSMEM    (OFF_B + 2 * B_CHUNK)      // 184320

__global__ __launch_bounds__(256, 1)
void vq_mma_kernel(const float* __restrict__ X) {
    extern __shared__ char smem[];
    const uint32_t sb = smem_to_u32(smem);
    const int tid  = threadIdx.x;
    const int lane = tid & 31;
    const int wid  = tid >> 5;
    const int g    = lane >> 2;
    const int t    = lane & 3;
    const int wm   = wid & 3;
    const int wn   = wid >> 2;
    const int mrow0 = wm * 32;
    const int ncol0 = wn * 64;
    const int brow  = blockIdx.x * 128;

    float* s_en = (float*)(smem + OFF_EN);
    #pragma unroll
    for (int i = 0; i < 4; i++) s_en[tid + i * 256] = g_enorm[tid + i * 256];

    // ---- prologue: resident A (hi+lo) + B chunk 0, one cp.async group ----
    for (int it = tid; it < 8192; it += 256) {
        int slab = it >> 12, rem = it & 4095;
        int row = rem >> 5, j = rem & 31;
        const __nv_bfloat16* src = ((slab == 0) ? g_xhi : g_xlo)
            + (size_t)(brow + row) * DIM + j * 8;
        CP_ASYNC16(sb + OFF_A + slab * A_SLAB + row * (A_STRIDE * 2) + j * 16, src);
    }
    for (int it = tid; it < 1024; it += 256) {
        int n = it >> 3, j = it & 7;
        CP_ASYNC16(sb + OFF_B + n * (B_STRIDE * 2) + j * 16,
                   g_ehi + (size_t)n * DIM + j * 8);
    }
    CP_COMMIT();

    // ---- precomputed ldmatrix addresses ----
    // A x4 tiles: [rows 0-7|k0-7], [rows 8-15|k0-7], [rows 0-7|k8-15], [rows 8-15|k8-15]
    const int a_row  = mrow0 + (lane & 7) + ((lane >> 3) & 1) * 8;  // + mi*16
    const int a_koff = (lane >> 4) * 8;                              // bf16
    uint32_t aAddr[2][2];
    #pragma unroll
    for (int mi = 0; mi < 2; mi++)
        #pragma unroll
        for (int hl = 0; hl < 2; hl++)
            aAddr[mi][hl] = sb + OFF_A + hl * A_SLAB
                + (a_row + mi * 16) * (A_STRIDE * 2) + a_koff * 2;
    // B x4 tiles: b[0]=n0-7/k0-7, b[1]=n8-15/k0-7, b[2]=n0-7/k8-15, b[3]=n8-15/k8-15
    const int b_n    = ncol0 + ((lane >> 3) & 1) * 8 + (lane & 7);  // + nfp*16
    const int b_koff = (lane >> 4) * 8;
    uint32_t bAddr[4];
    #pragma unroll
    for (int nfp = 0; nfp < 4; nfp++)
        bAddr[nfp] = sb + OFF_B + (b_n + nfp * 16) * (B_STRIDE * 2) + b_koff * 2;

    float acc[2][8][4];
    #pragma unroll
    for (int mi = 0; mi < 2; mi++)
        #pragma unroll
        for (int nf = 0; nf < 8; nf++)
            #pragma unroll
            for (int c = 0; c < 4; c++) acc[mi][nf][c] = 0.f;

    float best[4], sec[4];
    int   bidv[4];
    #pragma unroll
    for (int r = 0; r < 4; r++) { best[r] = 3.0e38f; sec[r] = 3.0e38f; bidv[r] = 0; }

    for (int i = 0; i < 32; i++) {
        const int cb = i >> 2, ch = i & 3, buf = i & 1;

        if (i > 0) __syncthreads();          // prev compute done before refill
        if (i + 1 < 32) {
            const int cb2 = (i + 1) >> 2, ch2 = (i + 1) & 3, nb = (i + 1) & 1;
            for (int it = tid; it < 1024; it += 256) {
                int n = it >> 3, j = it & 7;
                CP_ASYNC16(sb + OFF_B + nb * B_CHUNK + n * (B_STRIDE * 2) + j * 16,
                           g_ehi + (size_t)(cb2 * 128 + n) * DIM + ch2 * 64 + j * 8);
            }
            CP_COMMIT();
            CP_WAIT(1);
        } else {
            CP_WAIT(0);
        }
        __syncthreads();

        // ---- compute chunk i : 4 k-steps of 16 ----
        const uint32_t aK   = (uint32_t)(ch * 64) * 2;   // byte offset in A k
        const uint32_t bBuf = (uint32_t)(buf * B_CHUNK);
        #pragma unroll
        for (int step = 0; step < 4; step++) {
            uint32_t a[2][2][4];
            #pragma unroll
            for (int mi = 0; mi < 2; mi++) {
                ldm_x4(a[mi][0], aAddr[mi][0] + aK + step * 32);
                ldm_x4(a[mi][1], aAddr[mi][1] + aK + step * 32);
            }
            #pragma unroll
            for (int nfp = 0; nfp < 4; nfp++) {
                uint32_t b[4];
                ldm_x4(b, bAddr[nfp] + bBuf + step * 32);
                // B k-halves pair as (b[0],b[2]) for n-block 0 and
                // (b[1],b[3]) for n-block 1.
                #pragma unroll
                for (int mi = 0; mi < 2; mi++) {
                    mma_bf16(acc[mi][nfp * 2],     a[mi][0], b[0], b[2]);
                    mma_bf16(acc[mi][nfp * 2],     a[mi][1], b[0], b[2]);
                    mma_bf16(acc[mi][nfp * 2 + 1], a[mi][0], b[1], b[3]);
                    mma_bf16(acc[mi][nfp * 2 + 1], a[mi][1], b[1], b[3]);
                }
            }
        }

        if (ch == 3) {   // codeword tile done: fold into running argmin
            const int cbase = cb * 128 + ncol0;
            #pragma unroll
            for (int mi = 0; mi < 2; mi++) {
                #pragma unroll
                for (int nf = 0; nf < 8; nf++) {
                    const int colb = cbase + nf * 8 + 2 * t;
                    #pragma unroll
                    for (int h = 0; h < 2; h++) {
                        const int tr = mi * 2 + h;
                        float d0 = fmaf(-2.f, acc[mi][nf][h * 2 + 0], s_en[colb]);
                        float d1 = fmaf(-2.f, acc[mi][nf][h * 2 + 1], s_en[colb + 1]);
                        if (d0 < best[tr]) { sec[tr] = best[tr]; best[tr] = d0; bidv[tr] = colb; }
                        else if (d0 < sec[tr]) sec[tr] = d0;
                        if (d1 < best[tr]) { sec[tr] = best[tr]; best[tr] = d1; bidv[tr] = colb + 1; }
                        else if (d1 < sec[tr]) sec[tr] = d1;
                        acc[mi][nf][h * 2 + 0] = 0.f;
                        acc[mi][nf][h * 2 + 1] = 0.f;
                    }
                }
            }
        }
    }

    // ---- cross-thread merge (overlay scratch on B region) ----
    __syncthreads();
    float* mb = (float*)(smem + OFF_B);      // [row][slot] {best, sec, idx}
    const int slot = wn * 4 + t;
    #pragma unroll
    for (int mi = 0; mi < 2; mi++)
        #pragma unroll
        for (int h = 0; h < 2; h++) {
            int row = mrow0 + mi * 16 + h * 8 + g;
            int tr  = mi * 2 + h;
            int o   = (row * 8 + slot) * 3;
            mb[o] = best[tr]; mb[o + 1] = sec[tr]; ((int*)mb)[o + 2] = bidv[tr];
        }
    __syncthreads();

    if (tid < 128) {
        float gb = 3.0e38f; int gi = 0;
        #pragma unroll
        for (int s = 0; s < 8; s++) {
            int o = (tid * 8 + s) * 3;
            float v = mb[o]; int ix = ((int*)mb)[o + 2];
            if (v < gb || (v == gb && ix < gi)) { gb = v; gi = ix; }
        }
        float gs = 3.0e38f;
        #pragma unroll
        for (int s = 0; s < 8; s++) {
            int o = (tid * 8 + s) * 3;
            float v = mb[o], v2 = mb[o + 1]; int ix = ((int*)mb)[o + 2];
            float cand = (ix == gi) ? v2 : v;
            if (cand < gs) gs = cand;
        }
        int token = brow + tid;
        g_idx[token] = gi;
        if (gs - gb < MARGIN) {
            int p = atomicAdd(&g_nrcnt, 1);
            g_rlist[p] = token;
        }
    }
}

// ======================= kernel 3: exact fp32 recheck ======================
#define RG 16
__global__ __launch_bounds__(256)
void recheck_kernel(const float* __restrict__ X, const float* __restrict__ E) {
    __shared__ float xs[RG][DIM];
    __shared__ int   stok[RG];
    __shared__ float sv[256];
    __shared__ int   si[256];
    const int tid = threadIdx.x;
    const int cnt_total = g_nrcnt;
    const int ngroups = (cnt_total + RG - 1) / RG;

    for (int grp = blockIdx.x; grp < ngroups; grp += gridDim.x) {
        int base = grp * RG;
        __syncthreads();
        if (tid < RG) stok[tid] = (base + tid < cnt_total) ? g_rlist[base + tid] : -1;
        __syncthreads();
        #pragma unroll
        for (int r = 0; r < RG; r++) {
            int tk = stok[r];
            if (tk >= 0) xs[r][tid] = X[(size_t)tk * DIM + tid];
        }
        __syncthreads();

        float bv[RG]; int bi[RG];
        #pragma unroll
        for (int r = 0; r < RG; r++) { bv[r] = 3.0e38f; bi[r] = 0; }

        for (int c = 0; c < 4; c++) {
            int k = tid * 4 + c;
            float accr[RG];
            #pragma unroll
            for (int r = 0; r < RG; r++) accr[r] = 0.f;
            const float4* er = (const float4*)(E + (size_t)k * DIM);
            for (int j = 0; j < DIM / 4; j++) {
                float4 e4 = er[j];
                #pragma unroll
                for (int r = 0; r < RG; r++) {
                    float4 xv = *(const float4*)&xs[r][j * 4];
                    float a = accr[r];
                    a = fmaf(xv.x, e4.x, a);
                    a = fmaf(xv.y, e4.y, a);
                    a = fmaf(xv.z, e4.z, a);
                    a = fmaf(xv.w, e4.w, a);
                    accr[r] = a;
                }
            }
            float en = g_enorm[k];
            #pragma unroll
            for (int r = 0; r < RG; r++) {
                float d = fmaf(-2.f, accr[r], en);
                if (d < bv[r]) { bv[r] = d; bi[r] = k; }
            }
        }
        for (int r = 0; r < RG; r++) {
            sv[tid] = bv[r]; si[tid] = bi[r];
            __syncthreads();
            for (int st = 128; st > 0; st >>= 1) {
                if (tid < st) {
                    float v2 = sv[tid + st]; int i2 = si[tid + st];
                    if (v2 < sv[tid] || (v2 == sv[tid] && i2 < si[tid])) {
                        sv[tid] = v2; si[tid] = i2;
                    }
                }
                __syncthreads();
            }
            if (tid == 0 && stok[r] >= 0) g_idx[stok[r]] = si[0];
            __syncthreads();
        }
    }
}

// ======================= kernel 4: per-token epilogue ======================
__global__ __launch_bounds__(256)
void vq_epilogue_kernel(const float* __restrict__ X, const float* __restrict__ E,
                        float* __restrict__ out_q, float* __restrict__ out_idx,
                        float* __restrict__ out_enc) {
    const int t   = blockIdx.x;
    const int tid = threadIdx.x;
    const int idx = g_idx[t];

    if (tid == 0) {
        atomicAdd(&g_hist[idx], 1);
        out_idx[t] = (float)idx;
    }

    float q = E[(size_t)idx * DIM + tid];
    float x = X[(size_t)t   * DIM + tid];
    out_q[(size_t)t * DIM + tid] = q;

    float2 v0 = make_float2(0.f, 0.f);
    float2 v1 = make_float2(0.f, 0.f);
    if ((idx >> 2) == tid) {
        int sub = idx & 3;
        if (sub == 0) v0.x = 1.f;
        else if (sub == 1) v0.y = 1.f;
        else if (sub == 2) v1.x = 1.f;
        else v1.y = 1.f;
    }
    float* erow = out_enc + (size_t)t * KEMB + tid * 4;
    *(float2*)(erow)     = v0;
    *(float2*)(erow + 2) = v1;

    float d  = q - x;
    float sq = d * d;
    #pragma unroll
    for (int o = 16; o > 0; o >>= 1) sq += __shfl_xor_sync(0xFFFFFFFFu, sq, o);
    __shared__ float ws[8];
    if ((tid & 31) == 0) ws[tid >> 5] = sq;
    __syncthreads();
    if (tid == 0) {
        float s = 0.f;
        #pragma unroll
        for (int i = 0; i < 8; i++) s += ws[i];
        g_tokloss[t] = s;
    }
}

// ======================= kernel 5: finalize ================================
__global__ __launch_bounds__(256)
void vq_finalize_kernel(float* __restrict__ out_loss, float* __restrict__ out_perp) {
    __shared__ double sm[256];
    const int tid = threadIdx.x;

    double s = 0.0;
    for (int i = tid; i < N_TOK; i += 256) s += (double)g_tokloss[i];
    sm[tid] = s;
    __syncthreads();
    for (int st = 128; st > 0; st >>= 1) {
        if (tid < st) sm[tid] += sm[tid + st];
        __syncthreads();
    }
    if (tid == 0)
        out_loss[0] = (float)(0.25 * sm[0] / ((double)N_TOK * (double)DIM));
    __syncthreads();

    double p = 0.0;
    for (int i = tid; i < KEMB; i += 256) {
        double pk = (double)g_hist[i] / (double)N_TOK;
        p += pk * log(pk + 1e-10);
    }
    sm[tid] = p;
    __syncthreads();
    for (int st = 128; st > 0; st >>= 1) {
        if (tid < st) sm[tid] += sm[tid + st];
        __syncthreads();
    }
    if (tid == 0)
        out_perp[0] = (float)exp(-sm[0]);
}

// ---------------------------------------------------------------------------
extern "C" void kernel_launch(void* const* d_in, const int* in_sizes, int n_in,
                              void* d_out, int out_size) {
    const float* X = (const float*)d_in[0];
    const float* E = (const float*)d_in[1];
    if (n_in >= 2 && in_sizes[0] == KEMB * DIM && in_sizes[1] == N_TOK * DIM) {
        const float* tmp = X; X = E; E = tmp;
    }

    float* out      = (float*)d_out;
    float* out_loss = out;
    float* out_q    = out + 1;
    float* out_idx  = out + 1 + (size_t)N_TOK * DIM;
    float* out_perp = out_idx + N_TOK;
    float* out_enc  = out_perp + 1;

    cudaFuncSetAttribute(vq_mma_kernel,
                         cudaFuncAttributeMaxDynamicSharedMemorySize, GSMEM);

    convert_kernel    <<<N_TOK * DIM / 4 / 256, 256>>>(X);
    enorm_kernel      <<<128, 256>>>(E);
    vq_mma_kernel     <<<N_TOK / 128, 256, GSMEM>>>(X);
    recheck_kernel    <<<128, 256>>>(X, E);
    vq_epilogue_kernel<<<N_TOK, 256>>>(X, E, out_q, out_idx, out_enc);
    vq_finalize_kernel<<<1, 256>>>(out_loss, out_perp);
}

// round 7
// speedup vs baseline: 1.5060x; 1.0323x over previous
#include <cuda_runtime.h>
#include <cuda_bf16.h>
#include <math.h>
#include <stdint.h>

#define N_TOK 65536
#define DIM   256
#define KEMB  1024
#define MARGIN 0.025f

// ======================= helpers ===========================================
__device__ __forceinline__ uint32_t smem_to_u32(const void* p) {
    uint32_t a;
    asm("{ .reg .u64 t; cvta.to.shared.u64 t, %1; cvt.u32.u64 %0, t; }"
        : "=r"(a) : "l"(p));
    return a;
}
#define CP_ASYNC16(dst, src) \
    asm volatile("cp.async.cg.shared.global [%0], [%1], 16;" :: "r"(dst), "l"(src))
#define CP_COMMIT() asm volatile("cp.async.commit_group;" ::: "memory")
#define CP_WAIT(n)  asm volatile("cp.async.wait_group %0;" :: "n"(n) : "memory")

__device__ __forceinline__ void ldm_x4(uint32_t* r, uint32_t addr) {
    asm volatile("ldmatrix.sync.aligned.m8n8.x4.shared.b16 {%0,%1,%2,%3}, [%4];"
        : "=r"(r[0]), "=r"(r[1]), "=r"(r[2]), "=r"(r[3]) : "r"(addr));
}
__device__ __forceinline__ void mma_bf16(float* c, const uint32_t* a,
                                         uint32_t b0, uint32_t b1) {
    asm volatile(
        "mma.sync.aligned.m16n8k16.row.col.f32.bf16.bf16.f32 "
        "{%0,%1,%2,%3}, {%4,%5,%6,%7}, {%8,%9}, {%0,%1,%2,%3};"
        : "+f"(c[0]), "+f"(c[1]), "+f"(c[2]), "+f"(c[3])
        : "r"(a[0]), "r"(a[1]), "r"(a[2]), "r"(a[3]), "r"(b0), "r"(b1));
}

// ======================= device scratch ====================================
__device__ __align__(256) __nv_bfloat16 g_xhi[(size_t)N_TOK * DIM];
__device__ __align__(256) __nv_bfloat16 g_xlo[(size_t)N_TOK * DIM];
__device__ __align__(256) __nv_bfloat16 g_ehi[(size_t)KEMB * DIM];
__device__ __align__(256) __nv_bfloat16 g_elo[(size_t)KEMB * DIM];
__device__ float g_enorm[KEMB];
__device__ int   g_idx[N_TOK];
__device__ float g_tokloss[N_TOK / 4];
__device__ int   g_hist[KEMB];
__device__ int   g_nrcnt;
__device__ int   g_rlist[N_TOK];

// ======================= kernel 0: X split-bf16 conversion =================
__global__ __launch_bounds__(256)
void convert_kernel(const float* __restrict__ X) {
    size_t i = (size_t)blockIdx.x * 256 + threadIdx.x;   // float4 index
    float4 v = ((const float4*)X)[i];
    union { __nv_bfloat16 h[4]; uint2 u; } hi, lo;
    hi.h[0] = __float2bfloat16(v.x); lo.h[0] = __float2bfloat16(v.x - __bfloat162float(hi.h[0]));
    hi.h[1] = __float2bfloat16(v.y); lo.h[1] = __float2bfloat16(v.y - __bfloat162float(hi.h[1]));
    hi.h[2] = __float2bfloat16(v.z); lo.h[2] = __float2bfloat16(v.z - __bfloat162float(hi.h[2]));
    hi.h[3] = __float2bfloat16(v.w); lo.h[3] = __float2bfloat16(v.w - __bfloat162float(hi.h[3]));
    ((uint2*)g_xhi)[i] = hi.u;
    ((uint2*)g_xlo)[i] = lo.u;
}

// ======================= kernel 1: ||e||^2 + E->bf16 hi/lo + zeroing =======
__global__ __launch_bounds__(256)
void enorm_kernel(const float* __restrict__ E) {
    int warp = threadIdx.x >> 5;
    int lane = threadIdx.x & 31;
    int row  = blockIdx.x * 8 + warp;

    const float* r = E + (size_t)row * DIM;
    float s = 0.f;
    #pragma unroll
    for (int i = 0; i < DIM / 32; i++) {
        float v = r[lane + i * 32];
        __nv_bfloat16 h = __float2bfloat16(v);
        g_ehi[(size_t)row * DIM + lane + i * 32] = h;
        g_elo[(size_t)row * DIM + lane + i * 32] =
            __float2bfloat16(v - __bfloat162float(h));
        s = fmaf(v, v, s);
    }
    #pragma unroll
    for (int o = 16; o > 0; o >>= 1) s += __shfl_xor_sync(0xFFFFFFFFu, s, o);
    if (lane == 0) g_enorm[row] = s;

    int gid = blockIdx.x * blockDim.x + threadIdx.x;
    if (gid < KEMB) g_hist[gid] = 0;
    if (gid == 0)   g_nrcnt = 0;
}

// ======================= kernel 2: mma.sync distances + argmin =============
// 128 tokens / CTA.  A (xhi,xlo) resident.  B streamed: per iteration a
// 128cw x 64k chunk of BOTH ehi and elo (double buffered).  Per fragment:
// acc += xhi*ehi + xlo*ehi + xhi*elo  ->  x.e exact to the xlo*elo term
// (sigma ~ 1.7e-4), so MARGIN=0.025 covers >100 sigma.
#define A_STRIDE 264      // bf16, *2 = 528 B
#define B_STRIDE 88       // bf16, *2 = 176 B
#define A_SLAB   (128 * A_STRIDE * 2)       // 67584 B
#define B_CHUNK  (128 * B_STRIDE * 2)       // 22528 B (one of ehi|elo)
#define B_PAIR   (2 * B_CHUNK)              // 45056 B per buffer
#define OFF_EN   0
#define OFF_A    4096
#define OFF_B    (OFF_A + 2 * A_SLAB)       // 139264
#define GSMEM    (OFF_B + 2 * B_PAIR)       // 229376

__global__ __launch_bounds__(256, 1)
void vq_mma_kernel(const float* __restrict__ X) {
    extern __shared__ char smem[];
    const uint32_t sb = smem_to_u32(smem);
    const int tid  = threadIdx.x;
    const int lane = tid & 31;
    const int wid  = tid >> 5;
    const int g    = lane >> 2;
    const int t    = lane & 3;
    const int wm   = wid & 3;
    const int wn   = wid >> 2;
    const int mrow0 = wm * 32;
    const int ncol0 = wn * 64;
    const int brow  = blockIdx.x * 128;

    float* s_en = (float*)(smem + OFF_EN);
    #pragma unroll
    for (int i = 0; i < 4; i++) s_en[tid + i * 256] = g_enorm[tid + i * 256];

    // ---- prologue: resident A (hi+lo) + B pair 0 ----
    for (int it = tid; it < 8192; it += 256) {
        int slab = it >> 12, rem = it & 4095;
        int row = rem >> 5, j = rem & 31;
        const __nv_bfloat16* src = ((slab == 0) ? g_xhi : g_xlo)
            + (size_t)(brow + row) * DIM + j * 8;
        CP_ASYNC16(sb + OFF_A + slab * A_SLAB + row * (A_STRIDE * 2) + j * 16, src);
    }
    for (int it = tid; it < 2048; it += 256) {
        int half = it >> 10, rem = it & 1023;
        int n = rem >> 3, j = rem & 7;
        const __nv_bfloat16* src = ((half == 0) ? g_ehi : g_elo)
            + (size_t)n * DIM + j * 8;
        CP_ASYNC16(sb + OFF_B + half * B_CHUNK + n * (B_STRIDE * 2) + j * 16, src);
    }
    CP_COMMIT();

    // ---- precomputed ldmatrix addresses ----
    const int a_row  = mrow0 + (lane & 7) + ((lane >> 3) & 1) * 8;
    const int a_koff = (lane >> 4) * 8;
    uint32_t aAddr[2][2];
    #pragma unroll
    for (int mi = 0; mi < 2; mi++)
        #pragma unroll
        for (int hl = 0; hl < 2; hl++)
            aAddr[mi][hl] = sb + OFF_A + hl * A_SLAB
                + (a_row + mi * 16) * (A_STRIDE * 2) + a_koff * 2;
    const int b_n    = ncol0 + ((lane >> 3) & 1) * 8 + (lane & 7);
    const int b_koff = (lane >> 4) * 8;
    uint32_t bAddr[4];
    #pragma unroll
    for (int nfp = 0; nfp < 4; nfp++)
        bAddr[nfp] = sb + OFF_B + (b_n + nfp * 16) * (B_STRIDE * 2) + b_koff * 2;

    float acc[2][8][4];
    #pragma unroll
    for (int mi = 0; mi < 2; mi++)
        #pragma unroll
        for (int nf = 0; nf < 8; nf++)
            #pragma unroll
            for (int c = 0; c < 4; c++) acc[mi][nf][c] = 0.f;

    float best[4], sec[4];
    int   bidv[4];
    #pragma unroll
    for (int r = 0; r < 4; r++) { best[r] = 3.0e38f; sec[r] = 3.0e38f; bidv[r] = 0; }

    for (int i = 0; i < 32; i++) {
        const int cb = i >> 2, ch = i & 3, buf = i & 1;

        if (i > 0) __syncthreads();
        if (i + 1 < 32) {
            const int cb2 = (i + 1) >> 2, ch2 = (i + 1) & 3, nb = (i + 1) & 1;
            for (int it = tid; it < 2048; it += 256) {
                int half = it >> 10, rem = it & 1023;
                int n = rem >> 3, j = rem & 7;
                const __nv_bfloat16* src = ((half == 0) ? g_ehi : g_elo)
                    + (size_t)(cb2 * 128 + n) * DIM + ch2 * 64 + j * 8;
                CP_ASYNC16(sb + OFF_B + nb * B_PAIR + half * B_CHUNK
                           + n * (B_STRIDE * 2) + j * 16, src);
            }
            CP_COMMIT();
            CP_WAIT(1);
        } else {
            CP_WAIT(0);
        }
        __syncthreads();

        // ---- compute chunk i : 4 k-steps of 16 ----
        const uint32_t aK   = (uint32_t)(ch * 64) * 2;
        const uint32_t bBuf = (uint32_t)(buf * B_PAIR);
        #pragma unroll
        for (int step = 0; step < 4; step++) {
            uint32_t ahi[2][4], alo[2][4];
            #pragma unroll
            for (int mi = 0; mi < 2; mi++) {
                ldm_x4(ahi[mi], aAddr[mi][0] + aK + step * 32);
                ldm_x4(alo[mi], aAddr[mi][1] + aK + step * 32);
            }
            #pragma unroll
            for (int nfp = 0; nfp < 4; nfp++) {
                uint32_t bh[4], bl[4];
                ldm_x4(bh, bAddr[nfp] + bBuf + step * 32);
                ldm_x4(bl, bAddr[nfp] + bBuf + B_CHUNK + step * 32);
                // k-half pairing: (b[0],b[2]) n-block 0, (b[1],b[3]) n-block 1
                #pragma unroll
                for (int mi = 0; mi < 2; mi++) {
                    mma_bf16(acc[mi][nfp * 2],     ahi[mi], bh[0], bh[2]);
                    mma_bf16(acc[mi][nfp * 2],     alo[mi], bh[0], bh[2]);
                    mma_bf16(acc[mi][nfp * 2],     ahi[mi], bl[0], bl[2]);
                    mma_bf16(acc[mi][nfp * 2 + 1], ahi[mi], bh[1], bh[3]);
                    mma_bf16(acc[mi][nfp * 2 + 1], alo[mi], bh[1], bh[3]);
                    mma_bf16(acc[mi][nfp * 2 + 1], ahi[mi], bl[1], bl[3]);
                }
            }
        }

        if (ch == 3) {   // codeword tile done: fold into running argmin
            const int cbase = cb * 128 + ncol0;
            #pragma unroll
            for (int mi = 0; mi < 2; mi++) {
                #pragma unroll
                for (int nf = 0; nf < 8; nf++) {
                    const int colb = cbase + nf * 8 + 2 * t;
                    #pragma unroll
                    for (int h = 0; h < 2; h++) {
                        const int tr = mi * 2 + h;
                        float d0 = fmaf(-2.f, acc[mi][nf][h * 2 + 0], s_en[colb]);
                        float d1 = fmaf(-2.f, acc[mi][nf][h * 2 + 1], s_en[colb + 1]);
                        if (d0 < best[tr]) { sec[tr] = best[tr]; best[tr] = d0; bidv[tr] = colb; }
                        else if (d0 < sec[tr]) sec[tr] = d0;
                        if (d1 < best[tr]) { sec[tr] = best[tr]; best[tr] = d1; bidv[tr] = colb + 1; }
                        else if (d1 < sec[tr]) sec[tr] = d1;
                        acc[mi][nf][h * 2 + 0] = 0.f;
                        acc[mi][nf][h * 2 + 1] = 0.f;
                    }
                }
            }
        }
    }

    // ---- cross-thread merge (overlay scratch on B region) ----
    __syncthreads();
    float* mb = (float*)(smem + OFF_B);      // [row][slot] {best, sec, idx}
    const int slot = wn * 4 + t;
    #pragma unroll
    for (int mi = 0; mi < 2; mi++)
        #pragma unroll
        for (int h = 0; h < 2; h++) {
            int row = mrow0 + mi * 16 + h * 8 + g;
            int tr  = mi * 2 + h;
            int o   = (row * 8 + slot) * 3;
            mb[o] = best[tr]; mb[o + 1] = sec[tr]; ((int*)mb)[o + 2] = bidv[tr];
        }
    __syncthreads();

    if (tid < 128) {
        float gb = 3.0e38f; int gi = 0;
        #pragma unroll
        for (int s = 0; s < 8; s++) {
            int o = (tid * 8 + s) * 3;
            float v = mb[o]; int ix = ((int*)mb)[o + 2];
            if (v < gb || (v == gb && ix < gi)) { gb = v; gi = ix; }
        }
        float gs = 3.0e38f;
        #pragma unroll
        for (int s = 0; s < 8; s++) {
            int o = (tid * 8 + s) * 3;
            float v = mb[o], v2 = mb[o + 1]; int ix = ((int*)mb)[o + 2];
            float cand = (ix == gi) ? v2 : v;
            if (cand < gs) gs = cand;
        }
        int token = brow + tid;
        g_idx[token] = gi;
        if (gs - gb < MARGIN) {
            int p = atomicAdd(&g_nrcnt, 1);
            g_rlist[p] = token;
        }
    }
}

// ======================= kernel 3: exact fp32 recheck ======================
#define RG 16
__global__ __launch_bounds__(256)
void recheck_kernel(const float* __restrict__ X, const float* __restrict__ E) {
    __shared__ float xs[RG][DIM];
    __shared__ int   stok[RG];
    __shared__ float sv[256];
    __shared__ int   si[256];
    const int tid = threadIdx.x;
    const int cnt_total = g_nrcnt;
    const int ngroups = (cnt_total + RG - 1) / RG;

    for (int grp = blockIdx.x; grp < ngroups; grp += gridDim.x) {
        int base = grp * RG;
        __syncthreads();
        if (tid < RG) stok[tid] = (base + tid < cnt_total) ? g_rlist[base + tid] : -1;
        __syncthreads();
        #pragma unroll
        for (int r = 0; r < RG; r++) {
            int tk = stok[r];
            if (tk >= 0) xs[r][tid] = X[(size_t)tk * DIM + tid];
        }
        __syncthreads();

        float bv[RG]; int bi[RG];
        #pragma unroll
        for (int r = 0; r < RG; r++) { bv[r] = 3.0e38f; bi[r] = 0; }

        for (int c = 0; c < 4; c++) {
            int k = tid * 4 + c;
            float accr[RG];
            #pragma unroll
            for (int r = 0; r < RG; r++) accr[r] = 0.f;
            const float4* er = (const float4*)(E + (size_t)k * DIM);
            for (int j = 0; j < DIM / 4; j++) {
                float4 e4 = er[j];
                #pragma unroll
                for (int r = 0; r < RG; r++) {
                    float4 xv = *(const float4*)&xs[r][j * 4];
                    float a = accr[r];
                    a = fmaf(xv.x, e4.x, a);
                    a = fmaf(xv.y, e4.y, a);
                    a = fmaf(xv.z, e4.z, a);
                    a = fmaf(xv.w, e4.w, a);
                    accr[r] = a;
                }
            }
            float en = g_enorm[k];
            #pragma unroll
            for (int r = 0; r < RG; r++) {
                float d = fmaf(-2.f, accr[r], en);
                if (d < bv[r]) { bv[r] = d; bi[r] = k; }
            }
        }
        for (int r = 0; r < RG; r++) {
            sv[tid] = bv[r]; si[tid] = bi[r];
            __syncthreads();
            for (int st = 128; st > 0; st >>= 1) {
                if (tid < st) {
                    float v2 = sv[tid + st]; int i2 = si[tid + st];
                    if (v2 < sv[tid] || (v2 == sv[tid] && i2 < si[tid])) {
                        sv[tid] = v2; si[tid] = i2;
                    }
                }
                __syncthreads();
            }
            if (tid == 0 && stok[r] >= 0) g_idx[stok[r]] = si[0];
            __syncthreads();
        }
    }
}

// ======================= kernel 4: per-token epilogue (4 tokens/block) =====
__global__ __launch_bounds__(256)
void vq_epilogue_kernel(const float* __restrict__ X, const float* __restrict__ E,
                        float* __restrict__ out_q, float* __restrict__ out_idx,
                        float* __restrict__ out_enc) {
    const int tid  = threadIdx.x;
    const int base = blockIdx.x * 4;

    float sq = 0.f;
    #pragma unroll
    for (int tk = 0; tk < 4; tk++) {
        const int t   = base + tk;
        const int idx = g_idx[t];

        if (tid == 0) {
            atomicAdd(&g_hist[idx], 1);
            out_idx[t] = (float)idx;
        }

        float q = E[(size_t)idx * DIM + tid];
        float x = X[(size_t)t   * DIM + tid];
        out_q[(size_t)t * DIM + tid] = q;
        float d = q - x;
        sq = fmaf(d, d, sq);

        // encodings: interior [2,1022) as float4 (16B aligned since the row
        // base is ≡2 mod 4 floats), edges by thread 255.
        float* erow = out_enc + (size_t)t * KEMB;
        if (tid < 255) {
            const int sbase = 2 + tid * 4;
            float4 v;
            v.x = (idx == sbase)     ? 1.f : 0.f;
            v.y = (idx == sbase + 1) ? 1.f : 0.f;
            v.z = (idx == sbase + 2) ? 1.f : 0.f;
            v.w = (idx == sbase + 3) ? 1.f : 0.f;
            *(float4*)(erow + sbase) = v;
        } else {
            erow[0]    = (idx == 0)    ? 1.f : 0.f;
            erow[1]    = (idx == 1)    ? 1.f : 0.f;
            erow[1022] = (idx == 1022) ? 1.f : 0.f;
            erow[1023] = (idx == 1023) ? 1.f : 0.f;
        }
    }

    #pragma unroll
    for (int o = 16; o > 0; o >>= 1) sq += __shfl_xor_sync(0xFFFFFFFFu, sq, o);
    __shared__ float ws[8];
    if ((tid & 31) == 0) ws[tid >> 5] = sq;
    __syncthreads();
    if (tid == 0) {
        float s = 0.f;
        #pragma unroll
        for (int i = 0; i < 8; i++) s += ws[i];
        g_tokloss[blockIdx.x] = s;
    }
}

// ======================= kernel 5: finalize ================================
__global__ __launch_bounds__(256)
void vq_finalize_kernel(float* __restrict__ out_loss, float* __restrict__ out_perp) {
    __shared__ double sm[256];
    const int tid = threadIdx.x;

    double s = 0.0;
    for (int i = tid; i < N_TOK / 4; i += 256) s += (double)g_tokloss[i];
    sm[tid] = s;
    __syncthreads();
    for (int st = 128; st > 0; st >>= 1) {
        if (tid < st) sm[tid] += sm[tid + st];
        __syncthreads();
    }
    if (tid == 0)
        out_loss[0] = (float)(0.25 * sm[0] / ((double)N_TOK * (double)DIM));
    __syncthreads();

    double p = 0.0;
    for (int i = tid; i < KEMB; i += 256) {
        double pk = (double)g_hist[i] / (double)N_TOK;
        p += pk * log(pk + 1e-10);
    }
    sm[tid] = p;
    __syncthreads();
    for (int st = 128; st > 0; st >>= 1) {
        if (tid < st) sm[tid] += sm[tid + st];
        __syncthreads();
    }
    if (tid == 0)
        out_perp[0] = (float)exp(-sm[0]);
}

// ---------------------------------------------------------------------------
extern "C" void kernel_launch(void* const* d_in, const int* in_sizes, int n_in,
                              void* d_out, int out_size) {
    const float* X = (const float*)d_in[0];
    const float* E = (const float*)d_in[1];
    if (n_in >= 2 && in_sizes[0] == KEMB * DIM && in_sizes[1] == N_TOK * DIM) {
        const float* tmp = X; X = E; E = tmp;
    }

    float* out      = (float*)d_out;
    float* out_loss = out;
    float* out_q    = out + 1;
    float* out_idx  = out + 1 + (size_t)N_TOK * DIM;
    float* out_perp = out_idx + N_TOK;
    float* out_enc  = out_perp + 1;

    cudaFuncSetAttribute(vq_mma_kernel,
                         cudaFuncAttributeMaxDynamicSharedMemorySize, GSMEM);

    convert_kernel    <<<N_TOK * DIM / 4 / 256, 256>>>(X);
    enorm_kernel      <<<128, 256>>>(E);
    vq_mma_kernel     <<<N_TOK / 128, 256, GSMEM>>>(X);
    recheck_kernel    <<<128, 256>>>(X, E);
    vq_epilogue_kernel<<<N_TOK / 4, 256>>>(X, E, out_q, out_idx, out_enc);
    vq_finalize_kernel<<<1, 256>>>(out_loss, out_perp);
}

// round 9
// speedup vs baseline: 1.6085x; 1.0681x over previous
#include <cuda_runtime.h>
#include <cuda_bf16.h>
#include <math.h>
#include <stdint.h>

#define N_TOK 65536
#define DIM   256
#define KEMB  1024
#define MARGIN 0.004f

// ======================= helpers ===========================================
__device__ __forceinline__ uint32_t smem_to_u32(const void* p) {
    uint32_t a;
    asm("{ .reg .u64 t; cvta.to.shared.u64 t, %1; cvt.u32.u64 %0, t; }"
        : "=r"(a) : "l"(p));
    return a;
}
#define CP_ASYNC16(dst, src) \
    asm volatile("cp.async.cg.shared.global [%0], [%1], 16;" :: "r"(dst), "l"(src))
#define CP_COMMIT() asm volatile("cp.async.commit_group;" ::: "memory")
#define CP_WAIT(n)  asm volatile("cp.async.wait_group %0;" :: "n"(n) : "memory")

__device__ __forceinline__ void ldm_x4(uint32_t* r, uint32_t addr) {
    asm volatile("ldmatrix.sync.aligned.m8n8.x4.shared.b16 {%0,%1,%2,%3}, [%4];"
        : "=r"(r[0]), "=r"(r[1]), "=r"(r[2]), "=r"(r[3]) : "r"(addr));
}
__device__ __forceinline__ void mma_bf16(float* c, const uint32_t* a,
                                         uint32_t b0, uint32_t b1) {
    asm volatile(
        "mma.sync.aligned.m16n8k16.row.col.f32.bf16.bf16.f32 "
        "{%0,%1,%2,%3}, {%4,%5,%6,%7}, {%8,%9}, {%0,%1,%2,%3};"
        : "+f"(c[0]), "+f"(c[1]), "+f"(c[2]), "+f"(c[3])
        : "r"(a[0]), "r"(a[1]), "r"(a[2]), "r"(a[3]), "r"(b0), "r"(b1));
}

// ======================= device scratch ====================================
__device__ __align__(256) __nv_bfloat16 g_xhi[(size_t)N_TOK * DIM];
__device__ __align__(256) __nv_bfloat16 g_xlo[(size_t)N_TOK * DIM];
__device__ __align__(256) __nv_bfloat16 g_ehi[(size_t)KEMB * DIM];
__device__ __align__(256) __nv_bfloat16 g_elo[(size_t)KEMB * DIM];
__device__ float g_enorm[KEMB];
__device__ int   g_idx[N_TOK];
__device__ float g_tokloss[N_TOK / 4];
__device__ int   g_hist[KEMB];
__device__ int   g_nrcnt;
__device__ int   g_rlist[N_TOK];

// ======================= kernel 0: X split-bf16 conversion =================
__global__ __launch_bounds__(256)
void convert_kernel(const float* __restrict__ X) {
    size_t i = (size_t)blockIdx.x * 256 + threadIdx.x;   // float4 index
    float4 v = ((const float4*)X)[i];
    union { __nv_bfloat16 h[4]; uint2 u; } hi, lo;
    hi.h[0] = __float2bfloat16(v.x); lo.h[0] = __float2bfloat16(v.x - __bfloat162float(hi.h[0]));
    hi.h[1] = __float2bfloat16(v.y); lo.h[1] = __float2bfloat16(v.y - __bfloat162float(hi.h[1]));
    hi.h[2] = __float2bfloat16(v.z); lo.h[2] = __float2bfloat16(v.z - __bfloat162float(hi.h[2]));
    hi.h[3] = __float2bfloat16(v.w); lo.h[3] = __float2bfloat16(v.w - __bfloat162float(hi.h[3]));
    ((uint2*)g_xhi)[i] = hi.u;
    ((uint2*)g_xlo)[i] = lo.u;
}

// ======================= kernel 1: ||e||^2 + E->bf16 hi/lo + zeroing =======
__global__ __launch_bounds__(256)
void enorm_kernel(const float* __restrict__ E) {
    int warp = threadIdx.x >> 5;
    int lane = threadIdx.x & 31;
    int row  = blockIdx.x * 8 + warp;

    const float* r = E + (size_t)row * DIM;
    float s = 0.f;
    #pragma unroll
    for (int i = 0; i < DIM / 32; i++) {
        float v = r[lane + i * 32];
        __nv_bfloat16 h = __float2bfloat16(v);
        g_ehi[(size_t)row * DIM + lane + i * 32] = h;
        g_elo[(size_t)row * DIM + lane + i * 32] =
            __float2bfloat16(v - __bfloat162float(h));
        s = fmaf(v, v, s);
    }
    #pragma unroll
    for (int o = 16; o > 0; o >>= 1) s += __shfl_xor_sync(0xFFFFFFFFu, s, o);
    if (lane == 0) g_enorm[row] = s;

    int gid = blockIdx.x * blockDim.x + threadIdx.x;
    if (gid < KEMB) g_hist[gid] = 0;
    if (gid == 0)   g_nrcnt = 0;
}

// ======================= kernel 2: mma.sync distances + argmin =============
#define A_STRIDE 264
#define B_STRIDE 88
#define A_SLAB   (128 * A_STRIDE * 2)
#define B_CHUNK  (128 * B_STRIDE * 2)
#define B_PAIR   (2 * B_CHUNK)
#define OFF_EN   0
#define OFF_A    4096
#define OFF_B    (OFF_A + 2 * A_SLAB)
#define GSMEM    (OFF_B + 2 * B_PAIR)

__global__ __launch_bounds__(256, 1)
void vq_mma_kernel(const float* __restrict__ X) {
    extern __shared__ char smem[];
    const uint32_t sb = smem_to_u32(smem);
    const int tid  = threadIdx.x;
    const int lane = tid & 31;
    const int wid  = tid >> 5;
    const int g    = lane >> 2;
    const int t    = lane & 3;
    const int wm   = wid & 3;
    const int wn   = wid >> 2;
    const int mrow0 = wm * 32;
    const int ncol0 = wn * 64;
    const int brow  = blockIdx.x * 128;

    float* s_en = (float*)(smem + OFF_EN);
    #pragma unroll
    for (int i = 0; i < 4; i++) s_en[tid + i * 256] = g_enorm[tid + i * 256];

    for (int it = tid; it < 8192; it += 256) {
        int slab = it >> 12, rem = it & 4095;
        int row = rem >> 5, j = rem & 31;
        const __nv_bfloat16* src = ((slab == 0) ? g_xhi : g_xlo)
            + (size_t)(brow + row) * DIM + j * 8;
        CP_ASYNC16(sb + OFF_A + slab * A_SLAB + row * (A_STRIDE * 2) + j * 16, src);
    }
    for (int it = tid; it < 2048; it += 256) {
        int half = it >> 10, rem = it & 1023;
        int n = rem >> 3, j = rem & 7;
        const __nv_bfloat16* src = ((half == 0) ? g_ehi : g_elo)
            + (size_t)n * DIM + j * 8;
        CP_ASYNC16(sb + OFF_B + half * B_CHUNK + n * (B_STRIDE * 2) + j * 16, src);
    }
    CP_COMMIT();

    const int a_row  = mrow0 + (lane & 7) + ((lane >> 3) & 1) * 8;
    const int a_koff = (lane >> 4) * 8;
    uint32_t aAddr[2][2];
    #pragma unroll
    for (int mi = 0; mi < 2; mi++)
        #pragma unroll
        for (int hl = 0; hl < 2; hl++)
            aAddr[mi][hl] = sb + OFF_A + hl * A_SLAB
                + (a_row + mi * 16) * (A_STRIDE * 2) + a_koff * 2;
    const int b_n    = ncol0 + ((lane >> 3) & 1) * 8 + (lane & 7);
    const int b_koff = (lane >> 4) * 8;
    uint32_t bAddr[4];
    #pragma unroll
    for (int nfp = 0; nfp < 4; nfp++)
        bAddr[nfp] = sb + OFF_B + (b_n + nfp * 16) * (B_STRIDE * 2) + b_koff * 2;

    float acc[2][8][4];
    #pragma unroll
    for (int mi = 0; mi < 2; mi++)
        #pragma unroll
        for (int nf = 0; nf < 8; nf++)
            #pragma unroll
            for (int c = 0; c < 4; c++) acc[mi][nf][c] = 0.f;

    float best[4], sec[4];
    int   bidv[4];
    #pragma unroll
    for (int r = 0; r < 4; r++) { best[r] = 3.0e38f; sec[r] = 3.0e38f; bidv[r] = 0; }

    for (int i = 0; i < 32; i++) {
        const int cb = i >> 2, ch = i & 3, buf = i & 1;

        if (i > 0) __syncthreads();
        if (i + 1 < 32) {
            const int cb2 = (i + 1) >> 2, ch2 = (i + 1) & 3, nb = (i + 1) & 1;
            for (int it = tid; it < 2048; it += 256) {
                int half = it >> 10, rem = it & 1023;
                int n = rem >> 3, j = rem & 7;
                const __nv_bfloat16* src = ((half == 0) ? g_ehi : g_elo)
                    + (size_t)(cb2 * 128 + n) * DIM + ch2 * 64 + j * 8;
                CP_ASYNC16(sb + OFF_B + nb * B_PAIR + half * B_CHUNK
                           + n * (B_STRIDE * 2) + j * 16, src);
            }
            CP_COMMIT();
            CP_WAIT(1);
        } else {
            CP_WAIT(0);
        }
        __syncthreads();

        const uint32_t aK   = (uint32_t)(ch * 64) * 2;
        const uint32_t bBuf = (uint32_t)(buf * B_PAIR);
        #pragma unroll
        for (int step = 0; step < 4; step++) {
            uint32_t ahi[2][4], alo[2][4];
            #pragma unroll
            for (int mi = 0; mi < 2; mi++) {
                ldm_x4(ahi[mi], aAddr[mi][0] + aK + step * 32);
                ldm_x4(alo[mi], aAddr[mi][1] + aK + step * 32);
            }
            #pragma unroll
            for (int nfp = 0; nfp < 4; nfp++) {
                uint32_t bh[4], bl[4];
                ldm_x4(bh, bAddr[nfp] + bBuf + step * 32);
                ldm_x4(bl, bAddr[nfp] + bBuf + B_CHUNK + step * 32);
                #pragma unroll
                for (int mi = 0; mi < 2; mi++) {
                    mma_bf16(acc[mi][nfp * 2],     ahi[mi], bh[0], bh[2]);
                    mma_bf16(acc[mi][nfp * 2],     alo[mi], bh[0], bh[2]);
                    mma_bf16(acc[mi][nfp * 2],     ahi[mi], bl[0], bl[2]);
                    mma_bf16(acc[mi][nfp * 2 + 1], ahi[mi], bh[1], bh[3]);
                    mma_bf16(acc[mi][nfp * 2 + 1], alo[mi], bh[1], bh[3]);
                    mma_bf16(acc[mi][nfp * 2 + 1], ahi[mi], bl[1], bl[3]);
                }
            }
        }

        if (ch == 3) {
            const int cbase = cb * 128 + ncol0;
            #pragma unroll
            for (int mi = 0; mi < 2; mi++) {
                #pragma unroll
                for (int nf = 0; nf < 8; nf++) {
                    const int colb = cbase + nf * 8 + 2 * t;
                    #pragma unroll
                    for (int h = 0; h < 2; h++) {
                        const int tr = mi * 2 + h;
                        float d0 = fmaf(-2.f, acc[mi][nf][h * 2 + 0], s_en[colb]);
                        float d1 = fmaf(-2.f, acc[mi][nf][h * 2 + 1], s_en[colb + 1]);
                        if (d0 < best[tr]) { sec[tr] = best[tr]; best[tr] = d0; bidv[tr] = colb; }
                        else if (d0 < sec[tr]) sec[tr] = d0;
                        if (d1 < best[tr]) { sec[tr] = best[tr]; best[tr] = d1; bidv[tr] = colb + 1; }
                        else if (d1 < sec[tr]) sec[tr] = d1;
                        acc[mi][nf][h * 2 + 0] = 0.f;
                        acc[mi][nf][h * 2 + 1] = 0.f;
                    }
                }
            }
        }
    }

    __syncthreads();
    float* mb = (float*)(smem + OFF_B);
    const int slot = wn * 4 + t;
    #pragma unroll
    for (int mi = 0; mi < 2; mi++)
        #pragma unroll
        for (int h = 0; h < 2; h++) {
            int row = mrow0 + mi * 16 + h * 8 + g;
            int tr  = mi * 2 + h;
            int o   = (row * 8 + slot) * 3;
            mb[o] = best[tr]; mb[o + 1] = sec[tr]; ((int*)mb)[o + 2] = bidv[tr];
        }
    __syncthreads();

    if (tid < 128) {
        float gb = 3.0e38f; int gi = 0;
        #pragma unroll
        for (int s = 0; s < 8; s++) {
            int o = (tid * 8 + s) * 3;
            float v = mb[o]; int ix = ((int*)mb)[o + 2];
            if (v < gb || (v == gb && ix < gi)) { gb = v; gi = ix; }
        }
        float gs = 3.0e38f;
        #pragma unroll
        for (int s = 0; s < 8; s++) {
            int o = (tid * 8 + s) * 3;
            float v = mb[o], v2 = mb[o + 1]; int ix = ((int*)mb)[o + 2];
            float cand = (ix == gi) ? v2 : v;
            if (cand < gs) gs = cand;
        }
        int token = brow + tid;
        g_idx[token] = gi;
        if (gs - gb < MARGIN) {
            int p = atomicAdd(&g_nrcnt, 1);
            g_rlist[p] = token;
        }
    }
}

// ======================= kernel 3: exact fp32 recheck (parallel) ===========
// 8 tokens/block, thread handles 4 codewords (k = tid*4+c) for all 8 tokens.
// xs reads are warp-broadcast LDS; E streams from L2 (1MB, hot).
#define RG2 8
__global__ __launch_bounds__(256)
void recheck_kernel(const float* __restrict__ X, const float* __restrict__ E) {
    __shared__ float xs[RG2][DIM];
    __shared__ int   stok[RG2];
    __shared__ float sv[256];
    __shared__ int   si[256];
    const int tid = threadIdx.x;
    const int cnt_total = g_nrcnt;
    const int ngroups = (cnt_total + RG2 - 1) / RG2;

    for (int grp = blockIdx.x; grp < ngroups; grp += gridDim.x) {
        __syncthreads();   // prior iteration's smem users done
        int base = grp * RG2;
        if (tid < RG2) stok[tid] = (base + tid < cnt_total) ? g_rlist[base + tid] : -1;
        __syncthreads();
        #pragma unroll
        for (int r = 0; r < RG2; r++) {
            int tk = stok[r];
            if (tk >= 0) xs[r][tid] = X[(size_t)tk * DIM + tid];
        }
        __syncthreads();

        float acc[RG2][4];
        #pragma unroll
        for (int r = 0; r < RG2; r++)
            #pragma unroll
            for (int c = 0; c < 4; c++) acc[r][c] = 0.f;

        const float4* e0 = (const float4*)(E + (size_t)(tid * 4 + 0) * DIM);
        const float4* e1 = (const float4*)(E + (size_t)(tid * 4 + 1) * DIM);
        const float4* e2 = (const float4*)(E + (size_t)(tid * 4 + 2) * DIM);
        const float4* e3 = (const float4*)(E + (size_t)(tid * 4 + 3) * DIM);

        #pragma unroll 4
        for (int j = 0; j < DIM / 4; j++) {
            float4 ev[4];
            ev[0] = e0[j]; ev[1] = e1[j]; ev[2] = e2[j]; ev[3] = e3[j];
            #pragma unroll
            for (int r = 0; r < RG2; r++) {
                float4 xv = *(const float4*)&xs[r][j * 4];   // broadcast
                #pragma unroll
                for (int c = 0; c < 4; c++) {
                    float a = acc[r][c];
                    a = fmaf(xv.x, ev[c].x, a);
                    a = fmaf(xv.y, ev[c].y, a);
                    a = fmaf(xv.z, ev[c].z, a);
                    a = fmaf(xv.w, ev[c].w, a);
                    acc[r][c] = a;
                }
            }
        }

        float en[4];
        #pragma unroll
        for (int c = 0; c < 4; c++) en[c] = g_enorm[tid * 4 + c];

        float bv[RG2]; int bi[RG2];
        #pragma unroll
        for (int r = 0; r < RG2; r++) {
            bv[r] = 3.0e38f; bi[r] = 0;
            #pragma unroll
            for (int c = 0; c < 4; c++) {   // ascending k -> strict < keeps first
                float d = fmaf(-2.f, acc[r][c], en[c]);
                if (d < bv[r]) { bv[r] = d; bi[r] = tid * 4 + c; }
            }
        }

        #pragma unroll
        for (int r = 0; r < RG2; r++) {
            sv[tid] = bv[r]; si[tid] = bi[r];
            __syncthreads();
            for (int st = 128; st > 0; st >>= 1) {
                if (tid < st) {
                    float v2 = sv[tid + st]; int i2 = si[tid + st];
                    if (v2 < sv[tid] || (v2 == sv[tid] && i2 < si[tid])) {
                        sv[tid] = v2; si[tid] = i2;
                    }
                }
                __syncthreads();
            }
            if (tid == 0 && stok[r] >= 0) g_idx[stok[r]] = si[0];
            __syncthreads();
        }
    }
}

// ======================= kernel 4: zero out_enc (aligned float4) ===========
__global__ __launch_bounds__(256)
void zero_enc_kernel(float* __restrict__ out_enc) {
    const size_t n4 = ((size_t)N_TOK * KEMB - 4) / 4;   // interior float4s
    float4* p = (float4*)(out_enc + 2);                 // 16B aligned
    float4 z = make_float4(0.f, 0.f, 0.f, 0.f);
    size_t stride = (size_t)gridDim.x * blockDim.x;
    for (size_t i = (size_t)blockIdx.x * blockDim.x + threadIdx.x; i < n4; i += stride)
        p[i] = z;
    if (blockIdx.x == 0 && threadIdx.x == 0) {
        out_enc[0] = 0.f; out_enc[1] = 0.f;
        out_enc[(size_t)N_TOK * KEMB - 2] = 0.f;
        out_enc[(size_t)N_TOK * KEMB - 1] = 0.f;
    }
}

// ======================= kernel 5: scatter ones + idx + hist ===============
__global__ __launch_bounds__(256)
void scatter_kernel(float* __restrict__ out_idx, float* __restrict__ out_enc) {
    int t = blockIdx.x * 256 + threadIdx.x;
    int idx = g_idx[t];
    out_idx[t] = (float)idx;
    out_enc[(size_t)t * KEMB + idx] = 1.0f;
    atomicAdd(&g_hist[idx], 1);
}

// ======================= kernel 6: gather out_q + loss (4 tokens/block) ====
__global__ __launch_bounds__(256)
void gather_kernel(const float* __restrict__ X, const float* __restrict__ E,
                   float* __restrict__ out_q) {
    const int tid  = threadIdx.x;
    const int base = blockIdx.x * 4;

    float sq = 0.f;
    #pragma unroll
    for (int tk = 0; tk < 4; tk++) {
        const int t   = base + tk;
        const int idx = g_idx[t];
        float q = E[(size_t)idx * DIM + tid];
        float x = X[(size_t)t   * DIM + tid];
        out_q[(size_t)t * DIM + tid] = q;
        float d = q - x;
        sq = fmaf(d, d, sq);
    }

    #pragma unroll
    for (int o = 16; o > 0; o >>= 1) sq += __shfl_xor_sync(0xFFFFFFFFu, sq, o);
    __shared__ float ws[8];
    if ((tid & 31) == 0) ws[tid >> 5] = sq;
    __syncthreads();
    if (tid == 0) {
        float s = 0.f;
        #pragma unroll
        for (int i = 0; i < 8; i++) s += ws[i];
        g_tokloss[blockIdx.x] = s;
    }
}

// ======================= kernel 7: finalize ================================
__global__ __launch_bounds__(256)
void vq_finalize_kernel(float* __restrict__ out_loss, float* __restrict__ out_perp) {
    __shared__ double sm[256];
    const int tid = threadIdx.x;

    double s = 0.0;
    for (int i = tid; i < N_TOK / 4; i += 256) s += (double)g_tokloss[i];
    sm[tid] = s;
    __syncthreads();
    for (int st = 128; st > 0; st >>= 1) {
        if (tid < st) sm[tid] += sm[tid + st];
        __syncthreads();
    }
    if (tid == 0)
        out_loss[0] = (float)(0.25 * sm[0] / ((double)N_TOK * (double)DIM));
    __syncthreads();

    double p = 0.0;
    for (int i = tid; i < KEMB; i += 256) {
        double pk = (double)g_hist[i] / (double)N_TOK;
        p += pk * log(pk + 1e-10);
    }
    sm[tid] = p;
    __syncthreads();
    for (int st = 128; st > 0; st >>= 1) {
        if (tid < st) sm[tid] += sm[tid + st];
        __syncthreads();
    }
    if (tid == 0)
        out_perp[0] = (float)exp(-sm[0]);
}

// ---------------------------------------------------------------------------
extern "C" void kernel_launch(void* const* d_in, const int* in_sizes, int n_in,
                              void* d_out, int out_size) {
    const float* X = (const float*)d_in[0];
    const float* E = (const float*)d_in[1];
    if (n_in >= 2 && in_sizes[0] == KEMB * DIM && in_sizes[1] == N_TOK * DIM) {
        const float* tmp = X; X = E; E = tmp;
    }

    float* out      = (float*)d_out;
    float* out_loss = out;
    float* out_q    = out + 1;
    float* out_idx  = out + 1 + (size_t)N_TOK * DIM;
    float* out_perp = out_idx + N_TOK;
    float* out_enc  = out_perp + 1;

    cudaFuncSetAttribute(vq_mma_kernel,
                         cudaFuncAttributeMaxDynamicSharedMemorySize, GSMEM);

    convert_kernel    <<<N_TOK * DIM / 4 / 256, 256>>>(X);
    enorm_kernel      <<<128, 256>>>(E);
    vq_mma_kernel     <<<N_TOK / 128, 256, GSMEM>>>(X);
    zero_enc_kernel   <<<8192, 256>>>(out_enc);
    recheck_kernel    <<<4096, 256>>>(X, E);
    scatter_kernel    <<<N_TOK / 256, 256>>>(out_idx, out_enc);
    gather_kernel     <<<N_TOK / 4, 256>>>(X, E, out_q);
    vq_finalize_kernel<<<1, 256>>>(out_loss, out_perp);
}

// round 10
// speedup vs baseline: 1.7741x; 1.1029x over previous
#include <cuda_runtime.h>
#include <cuda_bf16.h>
#include <math.h>
#include <stdint.h>

#define N_TOK 65536
#define DIM   256
#define KEMB  1024
#define MARGIN 0.004f

// ======================= helpers ===========================================
__device__ __forceinline__ uint32_t smem_to_u32(const void* p) {
    uint32_t a;
    asm("{ .reg .u64 t; cvta.to.shared.u64 t, %1; cvt.u32.u64 %0, t; }"
        : "=r"(a) : "l"(p));
    return a;
}
#define CP_ASYNC16(dst, src) \
    asm volatile("cp.async.cg.shared.global [%0], [%1], 16;" :: "r"(dst), "l"(src))
#define CP_COMMIT() asm volatile("cp.async.commit_group;" ::: "memory")
#define CP_WAIT(n)  asm volatile("cp.async.wait_group %0;" :: "n"(n) : "memory")

__device__ __forceinline__ void ldm_x4(uint32_t* r, uint32_t addr) {
    asm volatile("ldmatrix.sync.aligned.m8n8.x4.shared.b16 {%0,%1,%2,%3}, [%4];"
        : "=r"(r[0]), "=r"(r[1]), "=r"(r[2]), "=r"(r[3]) : "r"(addr));
}
__device__ __forceinline__ void mma_bf16(float* c, const uint32_t* a,
                                         uint32_t b0, uint32_t b1) {
    asm volatile(
        "mma.sync.aligned.m16n8k16.row.col.f32.bf16.bf16.f32 "
        "{%0,%1,%2,%3}, {%4,%5,%6,%7}, {%8,%9}, {%0,%1,%2,%3};"
        : "+f"(c[0]), "+f"(c[1]), "+f"(c[2]), "+f"(c[3])
        : "r"(a[0]), "r"(a[1]), "r"(a[2]), "r"(a[3]), "r"(b0), "r"(b1));
}

// ======================= device scratch ====================================
__device__ __align__(256) __nv_bfloat16 g_xhi[(size_t)N_TOK * DIM];
__device__ __align__(256) __nv_bfloat16 g_xlo[(size_t)N_TOK * DIM];
__device__ __align__(256) __nv_bfloat16 g_ehi[(size_t)KEMB * DIM];
__device__ __align__(256) __nv_bfloat16 g_elo[(size_t)KEMB * DIM];
__device__ float g_enorm[KEMB];
__device__ int   g_idx[N_TOK];
__device__ float g_tokloss[N_TOK / 4];
__device__ int   g_hist[KEMB];
__device__ int   g_nrcnt;
__device__ int   g_rlist[N_TOK];

// ======================= kernel 0: X split-bf16 conversion =================
__global__ __launch_bounds__(256)
void convert_kernel(const float* __restrict__ X) {
    size_t i = (size_t)blockIdx.x * 256 + threadIdx.x;
    float4 v = ((const float4*)X)[i];
    union { __nv_bfloat16 h[4]; uint2 u; } hi, lo;
    hi.h[0] = __float2bfloat16(v.x); lo.h[0] = __float2bfloat16(v.x - __bfloat162float(hi.h[0]));
    hi.h[1] = __float2bfloat16(v.y); lo.h[1] = __float2bfloat16(v.y - __bfloat162float(hi.h[1]));
    hi.h[2] = __float2bfloat16(v.z); lo.h[2] = __float2bfloat16(v.z - __bfloat162float(hi.h[2]));
    hi.h[3] = __float2bfloat16(v.w); lo.h[3] = __float2bfloat16(v.w - __bfloat162float(hi.h[3]));
    ((uint2*)g_xhi)[i] = hi.u;
    ((uint2*)g_xlo)[i] = lo.u;
}

// ======================= kernel 1: ||e||^2 + E->bf16 hi/lo + zeroing =======
__global__ __launch_bounds__(256)
void enorm_kernel(const float* __restrict__ E) {
    int warp = threadIdx.x >> 5;
    int lane = threadIdx.x & 31;
    int row  = blockIdx.x * 8 + warp;

    const float* r = E + (size_t)row * DIM;
    float s = 0.f;
    #pragma unroll
    for (int i = 0; i < DIM / 32; i++) {
        float v = r[lane + i * 32];
        __nv_bfloat16 h = __float2bfloat16(v);
        g_ehi[(size_t)row * DIM + lane + i * 32] = h;
        g_elo[(size_t)row * DIM + lane + i * 32] =
            __float2bfloat16(v - __bfloat162float(h));
        s = fmaf(v, v, s);
    }
    #pragma unroll
    for (int o = 16; o > 0; o >>= 1) s += __shfl_xor_sync(0xFFFFFFFFu, s, o);
    if (lane == 0) g_enorm[row] = s;

    int gid = blockIdx.x * blockDim.x + threadIdx.x;
    if (gid < KEMB) g_hist[gid] = 0;
    if (gid == 0)   g_nrcnt = 0;
}

// ======================= kernel 2: mma.sync distances + argmin =============
// 64 tokens / CTA (1024 CTAs), 2 CTAs/SM.  A (xhi,xlo) resident (67.5KB).
// B streamed in 128cw x 32k chunks of (ehi,elo), double buffered (40KB).
// 8 warps: wm=wid&1 (32 rows), wn=wid>>1 (32 cols).  Per fragment:
// acc += xhi*ehi + xlo*ehi + xhi*elo.
#define A_STRIDE 264                        // bf16 -> 528 B (33*16)
#define A_SLAB   (64 * A_STRIDE * 2)        // 33792 B
#define B_STRIDE 40                         // bf16 -> 80 B (5*16)
#define B_CHUNK  (128 * B_STRIDE * 2)       // 10240 B (one of ehi|elo)
#define B_PAIR   (2 * B_CHUNK)              // 20480 B per buffer
#define OFF_EN   0
#define OFF_A    4096
#define OFF_B    (OFF_A + 2 * A_SLAB)       // 71680
#define GSMEM    (OFF_B + 2 * B_PAIR)       // 112640  (2 CTAs/SM)

__global__ __launch_bounds__(256, 2)
void vq_mma_kernel(const float* __restrict__ X) {
    extern __shared__ char smem[];
    const uint32_t sb = smem_to_u32(smem);
    const int tid  = threadIdx.x;
    const int lane = tid & 31;
    const int wid  = tid >> 5;
    const int g    = lane >> 2;
    const int t    = lane & 3;
    const int wm   = wid & 1;
    const int wn   = wid >> 1;
    const int mrow0 = wm * 32;
    const int ncol0 = wn * 32;
    const int brow  = blockIdx.x * 64;

    float* s_en = (float*)(smem + OFF_EN);
    #pragma unroll
    for (int i = 0; i < 4; i++) s_en[tid + i * 256] = g_enorm[tid + i * 256];

    // ---- prologue: resident A (hi+lo) + B chunk 0 ----
    for (int it = tid; it < 4096; it += 256) {
        int slab = it >> 11, rem = it & 2047;
        int row = rem >> 5, j = rem & 31;
        const __nv_bfloat16* src = ((slab == 0) ? g_xhi : g_xlo)
            + (size_t)(brow + row) * DIM + j * 8;
        CP_ASYNC16(sb + OFF_A + slab * A_SLAB + row * (A_STRIDE * 2) + j * 16, src);
    }
    for (int it = tid; it < 1024; it += 256) {
        int half = it >> 9, rem = it & 511;
        int n = rem >> 2, j = rem & 3;
        const __nv_bfloat16* src = ((half == 0) ? g_ehi : g_elo)
            + (size_t)n * DIM + j * 8;
        CP_ASYNC16(sb + OFF_B + half * B_CHUNK + n * (B_STRIDE * 2) + j * 16, src);
    }
    CP_COMMIT();

    // ---- precomputed ldmatrix addresses ----
    const int a_row  = mrow0 + (lane & 7) + ((lane >> 3) & 1) * 8;   // + mi*16
    const int a_koff = (lane >> 4) * 8;
    uint32_t aAddr[2][2];
    #pragma unroll
    for (int mi = 0; mi < 2; mi++)
        #pragma unroll
        for (int hl = 0; hl < 2; hl++)
            aAddr[mi][hl] = sb + OFF_A + hl * A_SLAB
                + (a_row + mi * 16) * (A_STRIDE * 2) + a_koff * 2;
    const int b_n    = ncol0 + ((lane >> 3) & 1) * 8 + (lane & 7);   // + nfp*16
    const int b_koff = (lane >> 4) * 8;
    uint32_t bAddr[2];
    #pragma unroll
    for (int nfp = 0; nfp < 2; nfp++)
        bAddr[nfp] = sb + OFF_B + (b_n + nfp * 16) * (B_STRIDE * 2) + b_koff * 2;

    float acc[2][4][4];
    #pragma unroll
    for (int mi = 0; mi < 2; mi++)
        #pragma unroll
        for (int nf = 0; nf < 4; nf++)
            #pragma unroll
            for (int c = 0; c < 4; c++) acc[mi][nf][c] = 0.f;

    float best[4], sec[4];
    int   bidv[4];
    #pragma unroll
    for (int r = 0; r < 4; r++) { best[r] = 3.0e38f; sec[r] = 3.0e38f; bidv[r] = 0; }

    for (int i = 0; i < 64; i++) {
        const int cb = i >> 3, ch = i & 7, buf = i & 1;

        if (i > 0) __syncthreads();          // prev compute done before refill
        if (i + 1 < 64) {
            const int cb2 = (i + 1) >> 3, ch2 = (i + 1) & 7, nb = (i + 1) & 1;
            for (int it = tid; it < 1024; it += 256) {
                int half = it >> 9, rem = it & 511;
                int n = rem >> 2, j = rem & 3;
                const __nv_bfloat16* src = ((half == 0) ? g_ehi : g_elo)
                    + (size_t)(cb2 * 128 + n) * DIM + ch2 * 32 + j * 8;
                CP_ASYNC16(sb + OFF_B + nb * B_PAIR + half * B_CHUNK
                           + n * (B_STRIDE * 2) + j * 16, src);
            }
            CP_COMMIT();
            CP_WAIT(1);
        } else {
            CP_WAIT(0);
        }
        __syncthreads();

        // ---- compute chunk i : 2 k-steps of 16 ----
        const uint32_t aK   = (uint32_t)(ch * 32) * 2;   // byte offset in A k
        const uint32_t bBuf = (uint32_t)(buf * B_PAIR);
        #pragma unroll
        for (int step = 0; step < 2; step++) {
            uint32_t ahi[2][4], alo[2][4];
            #pragma unroll
            for (int mi = 0; mi < 2; mi++) {
                ldm_x4(ahi[mi], aAddr[mi][0] + aK + step * 32);
                ldm_x4(alo[mi], aAddr[mi][1] + aK + step * 32);
            }
            #pragma unroll
            for (int nfp = 0; nfp < 2; nfp++) {
                uint32_t bh[4], bl[4];
                ldm_x4(bh, bAddr[nfp] + bBuf + step * 32);
                ldm_x4(bl, bAddr[nfp] + bBuf + B_CHUNK + step * 32);
                // k-half pairing: (b[0],b[2]) n-block 0, (b[1],b[3]) n-block 1
                #pragma unroll
                for (int mi = 0; mi < 2; mi++) {
                    mma_bf16(acc[mi][nfp * 2],     ahi[mi], bh[0], bh[2]);
                    mma_bf16(acc[mi][nfp * 2],     alo[mi], bh[0], bh[2]);
                    mma_bf16(acc[mi][nfp * 2],     ahi[mi], bl[0], bl[2]);
                    mma_bf16(acc[mi][nfp * 2 + 1], ahi[mi], bh[1], bh[3]);
                    mma_bf16(acc[mi][nfp * 2 + 1], alo[mi], bh[1], bh[3]);
                    mma_bf16(acc[mi][nfp * 2 + 1], ahi[mi], bl[1], bl[3]);
                }
            }
        }

        if (ch == 7) {   // codeword tile done: fold into running argmin
            const int cbase = cb * 128 + ncol0;
            #pragma unroll
            for (int mi = 0; mi < 2; mi++) {
                #pragma unroll
                for (int nf = 0; nf < 4; nf++) {
                    const int colb = cbase + nf * 8 + 2 * t;
                    #pragma unroll
                    for (int h = 0; h < 2; h++) {
                        const int tr = mi * 2 + h;
                        float d0 = fmaf(-2.f, acc[mi][nf][h * 2 + 0], s_en[colb]);
                        float d1 = fmaf(-2.f, acc[mi][nf][h * 2 + 1], s_en[colb + 1]);
                        if (d0 < best[tr]) { sec[tr] = best[tr]; best[tr] = d0; bidv[tr] = colb; }
                        else if (d0 < sec[tr]) sec[tr] = d0;
                        if (d1 < best[tr]) { sec[tr] = best[tr]; best[tr] = d1; bidv[tr] = colb + 1; }
                        else if (d1 < sec[tr]) sec[tr] = d1;
                        acc[mi][nf][h * 2 + 0] = 0.f;
                        acc[mi][nf][h * 2 + 1] = 0.f;
                    }
                }
            }
        }
    }

    // ---- cross-thread merge (overlay scratch on B region) ----
    __syncthreads();
    float* mb = (float*)(smem + OFF_B);      // [row][slot] {best, sec, idx}, 16 slots
    const int slot = wn * 4 + t;
    #pragma unroll
    for (int mi = 0; mi < 2; mi++)
        #pragma unroll
        for (int h = 0; h < 2; h++) {
            int row = mrow0 + mi * 16 + h * 8 + g;
            int tr  = mi * 2 + h;
            int o   = (row * 16 + slot) * 3;
            mb[o] = best[tr]; mb[o + 1] = sec[tr]; ((int*)mb)[o + 2] = bidv[tr];
        }
    __syncthreads();

    if (tid < 64) {
        float gb = 3.0e38f; int gi = 0;
        #pragma unroll
        for (int s = 0; s < 16; s++) {
            int o = (tid * 16 + s) * 3;
            float v = mb[o]; int ix = ((int*)mb)[o + 2];
            if (v < gb || (v == gb && ix < gi)) { gb = v; gi = ix; }
        }
        float gs = 3.0e38f;
        #pragma unroll
        for (int s = 0; s < 16; s++) {
            int o = (tid * 16 + s) * 3;
            float v = mb[o], v2 = mb[o + 1]; int ix = ((int*)mb)[o + 2];
            float cand = (ix == gi) ? v2 : v;
            if (cand < gs) gs = cand;
        }
        int token = brow + tid;
        g_idx[token] = gi;
        if (gs - gb < MARGIN) {
            int p = atomicAdd(&g_nrcnt, 1);
            g_rlist[p] = token;
        }
    }
}

// ======================= kernel 3: exact fp32 recheck (parallel) ===========
#define RG2 8
__global__ __launch_bounds__(256)
void recheck_kernel(const float* __restrict__ X, const float* __restrict__ E) {
    __shared__ float xs[RG2][DIM];
    __shared__ int   stok[RG2];
    __shared__ float sv[256];
    __shared__ int   si[256];
    const int tid = threadIdx.x;
    const int cnt_total = g_nrcnt;
    const int ngroups = (cnt_total + RG2 - 1) / RG2;

    for (int grp = blockIdx.x; grp < ngroups; grp += gridDim.x) {
        __syncthreads();
        int base = grp * RG2;
        if (tid < RG2) stok[tid] = (base + tid < cnt_total) ? g_rlist[base + tid] : -1;
        __syncthreads();
        #pragma unroll
        for (int r = 0; r < RG2; r++) {
            int tk = stok[r];
            if (tk >= 0) xs[r][tid] = X[(size_t)tk * DIM + tid];
        }
        __syncthreads();

        float acc[RG2][4];
        #pragma unroll
        for (int r = 0; r < RG2; r++)
            #pragma unroll
            for (int c = 0; c < 4; c++) acc[r][c] = 0.f;

        const float4* e0 = (const float4*)(E + (size_t)(tid * 4 + 0) * DIM);
        const float4* e1 = (const float4*)(E + (size_t)(tid * 4 + 1) * DIM);
        const float4* e2 = (const float4*)(E + (size_t)(tid * 4 + 2) * DIM);
        const float4* e3 = (const float4*)(E + (size_t)(tid * 4 + 3) * DIM);

        #pragma unroll 4
        for (int j = 0; j < DIM / 4; j++) {
            float4 ev[4];
            ev[0] = e0[j]; ev[1] = e1[j]; ev[2] = e2[j]; ev[3] = e3[j];
            #pragma unroll
            for (int r = 0; r < RG2; r++) {
                float4 xv = *(const float4*)&xs[r][j * 4];
                #pragma unroll
                for (int c = 0; c < 4; c++) {
                    float a = acc[r][c];
                    a = fmaf(xv.x, ev[c].x, a);
                    a = fmaf(xv.y, ev[c].y, a);
                    a = fmaf(xv.z, ev[c].z, a);
                    a = fmaf(xv.w, ev[c].w, a);
                    acc[r][c] = a;
                }
            }
        }

        float en[4];
        #pragma unroll
        for (int c = 0; c < 4; c++) en[c] = g_enorm[tid * 4 + c];

        float bv[RG2]; int bi[RG2];
        #pragma unroll
        for (int r = 0; r < RG2; r++) {
            bv[r] = 3.0e38f; bi[r] = 0;
            #pragma unroll
            for (int c = 0; c < 4; c++) {
                float d = fmaf(-2.f, acc[r][c], en[c]);
                if (d < bv[r]) { bv[r] = d; bi[r] = tid * 4 + c; }
            }
        }

        #pragma unroll
        for (int r = 0; r < RG2; r++) {
            sv[tid] = bv[r]; si[tid] = bi[r];
            __syncthreads();
            for (int st = 128; st > 0; st >>= 1) {
                if (tid < st) {
                    float v2 = sv[tid + st]; int i2 = si[tid + st];
                    if (v2 < sv[tid] || (v2 == sv[tid] && i2 < si[tid])) {
                        sv[tid] = v2; si[tid] = i2;
                    }
                }
                __syncthreads();
            }
            if (tid == 0 && stok[r] >= 0) g_idx[stok[r]] = si[0];
            __syncthreads();
        }
    }
}

// ======================= kernel 4: fused epilogue (4 tokens/block) =========
// Writes enc row once (zeros + one via predicated float4), q gather, idx,
// hist, per-block loss partial.
__global__ __launch_bounds__(256)
void vq_epilogue_kernel(const float* __restrict__ X, const float* __restrict__ E,
                        float* __restrict__ out_q, float* __restrict__ out_idx,
                        float* __restrict__ out_enc) {
    const int tid  = threadIdx.x;
    const int base = blockIdx.x * 4;

    float sq = 0.f;
    #pragma unroll
    for (int tk = 0; tk < 4; tk++) {
        const int t   = base + tk;
        const int idx = g_idx[t];

        if (tid == 0) {
            atomicAdd(&g_hist[idx], 1);
            out_idx[t] = (float)idx;
        }

        float q = E[(size_t)idx * DIM + tid];
        float x = X[(size_t)t   * DIM + tid];
        out_q[(size_t)t * DIM + tid] = q;
        float d = q - x;
        sq = fmaf(d, d, sq);

        // enc row: interior [2,1022) as float4 (16B aligned: row base ≡2 mod 4
        // floats), edges by thread 255.
        float* erow = out_enc + (size_t)t * KEMB;
        if (tid < 255) {
            const int sbase = 2 + tid * 4;
            float4 v;
            v.x = (idx == sbase)     ? 1.f : 0.f;
            v.y = (idx == sbase + 1) ? 1.f : 0.f;
            v.z = (idx == sbase + 2) ? 1.f : 0.f;
            v.w = (idx == sbase + 3) ? 1.f : 0.f;
            *(float4*)(erow + sbase) = v;
        } else {
            erow[0]    = (idx == 0)    ? 1.f : 0.f;
            erow[1]    = (idx == 1)    ? 1.f : 0.f;
            erow[1022] = (idx == 1022) ? 1.f : 0.f;
            erow[1023] = (idx == 1023) ? 1.f : 0.f;
        }
    }

    #pragma unroll
    for (int o = 16; o > 0; o >>= 1) sq += __shfl_xor_sync(0xFFFFFFFFu, sq, o);
    __shared__ float ws[8];
    if ((tid & 31) == 0) ws[tid >> 5] = sq;
    __syncthreads();
    if (tid == 0) {
        float s = 0.f;
        #pragma unroll
        for (int i = 0; i < 8; i++) s += ws[i];
        g_tokloss[blockIdx.x] = s;
    }
}

// ======================= kernel 5: finalize ================================
__global__ __launch_bounds__(256)
void vq_finalize_kernel(float* __restrict__ out_loss, float* __restrict__ out_perp) {
    __shared__ double sm[256];
    const int tid = threadIdx.x;

    double s = 0.0;
    for (int i = tid; i < N_TOK / 4; i += 256) s += (double)g_tokloss[i];
    sm[tid] = s;
    __syncthreads();
    for (int st = 128; st > 0; st >>= 1) {
        if (tid < st) sm[tid] += sm[tid + st];
        __syncthreads();
    }
    if (tid == 0)
        out_loss[0] = (float)(0.25 * sm[0] / ((double)N_TOK * (double)DIM));
    __syncthreads();

    double p = 0.0;
    for (int i = tid; i < KEMB; i += 256) {
        double pk = (double)g_hist[i] / (double)N_TOK;
        p += pk * log(pk + 1e-10);
    }
    sm[tid] = p;
    __syncthreads();
    for (int st = 128; st > 0; st >>= 1) {
        if (tid < st) sm[tid] += sm[tid + st];
        __syncthreads();
    }
    if (tid == 0)
        out_perp[0] = (float)exp(-sm[0]);
}

// ---------------------------------------------------------------------------
extern "C" void kernel_launch(void* const* d_in, const int* in_sizes, int n_in,
                              void* d_out, int out_size) {
    const float* X = (const float*)d_in[0];
    const float* E = (const float*)d_in[1];
    if (n_in >= 2 && in_sizes[0] == KEMB * DIM && in_sizes[1] == N_TOK * DIM) {
        const float* tmp = X; X = E; E = tmp;
    }

    float* out      = (float*)d_out;
    float* out_loss = out;
    float* out_q    = out + 1;
    float* out_idx  = out + 1 + (size_t)N_TOK * DIM;
    float* out_perp = out_idx + N_TOK;
    float* out_enc  = out_perp + 1;

    cudaFuncSetAttribute(vq_mma_kernel,
                         cudaFuncAttributeMaxDynamicSharedMemorySize, GSMEM);

    convert_kernel    <<<N_TOK * DIM / 4 / 256, 256>>>(X);
    enorm_kernel      <<<128, 256>>>(E);
    vq_mma_kernel     <<<N_TOK / 64, 256, GSMEM>>>(X);
    recheck_kernel    <<<4096, 256>>>(X, E);
    vq_epilogue_kernel<<<N_TOK / 4, 256>>>(X, E, out_q, out_idx, out_enc);
    vq_finalize_kernel<<<1, 256>>>(out_loss, out_perp);
}